// round 17
// baseline (speedup 1.0000x reference)
#include <cuda_runtime.h>
#include <math.h>
#include <string.h>

#define NSTEP  98
#define NSAVE  49
#define NROW   50   // table rows incl. identity row 0

// ---------------- constant table passed by value (constant memory) ----------
struct KTab {
    float4 a[NROW];   // {alpha+gamma, beta, gamma, 0};  a[0] = {1,0,0,0}
    float4 v[NROW];   // {V0, V1, V2, V3};               v[0] = 0
};

// ---------------- host: build the universal table in fp64 ------------------
static void host_tsit2(double u0, double d0, const double cs[6], double* ru, double* rd)
{
    const double h = 0.01;
    const double a21 = 0.161;
    const double a31 = -0.008480655492356989, a32 = 0.335480655492357;
    const double a41 = 2.8971530571054935, a42 = -6.359448489975075, a43 = 4.3622954328695815;
    const double a51 = 5.325864828439257, a52 = -11.748883564062828, a53 = 7.4955393428898365, a54 = -0.09249506636175525;
    const double a61 = 5.86145544294642, a62 = -12.92096931784711, a63 = 8.159367898576159, a64 = -0.071584973281401, a65 = -0.028269050394068383;
    const double b1 = 0.09646076681806523, b2 = 0.01, b3 = 0.4798896504144996,
                 b4 = 1.379008574103742, b5 = -3.290069515436081, b6 = 2.324710524099774;

    double ku[6], kd[6], su, sd;
    su = u0; sd = d0;
    ku[0] = sd; kd[0] = -25.0*su - 10.0*sd + cs[0];
    su = u0 + h*(a21*ku[0]);                               sd = d0 + h*(a21*kd[0]);
    ku[1] = sd; kd[1] = -25.0*su - 10.0*sd + cs[1];
    su = u0 + h*(a31*ku[0]+a32*ku[1]);                     sd = d0 + h*(a31*kd[0]+a32*kd[1]);
    ku[2] = sd; kd[2] = -25.0*su - 10.0*sd + cs[2];
    su = u0 + h*(a41*ku[0]+a42*ku[1]+a43*ku[2]);           sd = d0 + h*(a41*kd[0]+a42*kd[1]+a43*kd[2]);
    ku[3] = sd; kd[3] = -25.0*su - 10.0*sd + cs[3];
    su = u0 + h*(a51*ku[0]+a52*ku[1]+a53*ku[2]+a54*ku[3]); sd = d0 + h*(a51*kd[0]+a52*kd[1]+a53*kd[2]+a54*kd[3]);
    ku[4] = sd; kd[4] = -25.0*su - 10.0*sd + cs[4];
    su = u0 + h*(a61*ku[0]+a62*ku[1]+a63*ku[2]+a64*ku[3]+a65*ku[4]);
    sd = d0 + h*(a61*kd[0]+a62*kd[1]+a63*kd[2]+a64*kd[3]+a65*kd[4]);
    ku[5] = sd; kd[5] = -25.0*su - 10.0*sd + cs[5];

    *ru = u0 + h*(b1*ku[0]+b2*ku[1]+b3*ku[2]+b4*ku[3]+b5*ku[4]+b6*ku[5]);
    *rd = d0 + h*(b1*kd[0]+b2*kd[1]+b3*kd[2]+b4*kd[3]+b5*kd[4]+b6*kd[5]);
}

static void build_ktab(KTab* kt)
{
    const double h = 0.01;
    const double a21 = 0.161;
    const double a31 = -0.008480655492356989, a32 = 0.335480655492357;
    const double a41 = 2.8971530571054935, a42 = -6.359448489975075, a43 = 4.3622954328695815;
    const double a51 = 5.325864828439257, a52 = -11.748883564062828, a53 = 7.4955393428898365, a54 = -0.09249506636175525;
    const double a61 = 5.86145544294642, a62 = -12.92096931784711, a63 = 8.159367898576159, a64 = -0.071584973281401, a65 = -0.028269050394068383;
    const double b1 = 0.09646076681806523, b2 = 0.01, b3 = 0.4798896504144996,
                 b4 = 1.379008574103742, b5 = -3.290069515436081, b6 = 2.324710524099774;

    // scalar phase ODE p' = -p: stage factors sig[s], step factor R
    double k1 = -1.0;
    double p2 = 1.0 + h*a21*k1;                               double k2 = -p2;
    double p3 = 1.0 + h*(a31*k1+a32*k2);                      double k3 = -p3;
    double p4 = 1.0 + h*(a41*k1+a42*k2+a43*k3);               double k4 = -p4;
    double p5 = 1.0 + h*(a51*k1+a52*k2+a53*k3+a54*k4);        double k5 = -p5;
    double p6 = 1.0 + h*(a61*k1+a62*k2+a63*k3+a64*k4+a65*k5); double k6 = -p6;
    double sig[6] = {1.0, p2, p3, p4, p5, p6};
    double R = 1.0 + h*(b1*k1+b2*k2+b3*k3+b4*k4+b5*k5+b6*k6);

    double C[4], H[4];
    for (int k = 0; k < 4; k++) { C[k] = exp(-(double)k / 3.0); H[k] = 4.0 / C[k]; }

    // one-step matrices via superposition
    double M[2][2], E[2], D[6][2];
    double z[6] = {0,0,0,0,0,0};
    host_tsit2(1.0, 0.0, z, &M[0][0], &M[1][0]);
    host_tsit2(0.0, 1.0, z, &M[0][1], &M[1][1]);
    double cg[6] = {25.0,25.0,25.0,25.0,25.0,25.0};
    host_tsit2(0.0, 0.0, cg, &E[0], &E[1]);
    for (int s = 0; s < 6; s++) {
        double ci[6] = {0,0,0,0,0,0};
        ci[s] = 1.0;
        host_tsit2(0.0, 0.0, ci, &D[s][0], &D[s][1]);
    }

    // per-step forcing response
    static double Dlin[NSTEP][2][4];
    double pn = 1.0;
    for (int n = 0; n < NSTEP; n++) {
        double A0[4] = {0,0,0,0}, A1[4] = {0,0,0,0};
        for (int s = 0; s < 6; s++) {
            double ps = sig[s] * pn;
            double psi[4], sw = 0.0;
            for (int k = 0; k < 4; k++) {
                double d = ps - C[k];
                psi[k] = exp(-H[k] * d * d);
                sw += psi[k];
            }
            double sc = ps / sw;
            for (int k = 0; k < 4; k++) {
                double w = psi[k] * sc;
                A0[k] += D[s][0] * w;
                A1[k] += D[s][1] * w;
            }
        }
        for (int k = 0; k < 4; k++) { Dlin[n][0][k] = A0[k]; Dlin[n][1][k] = A1[k]; }
        pn *= R;
    }

    // row 0: identity (u_0 = u0)
    kt->a[0] = make_float4(1.0f, 0.0f, 0.0f, 0.0f);
    kt->v[0] = make_float4(0.0f, 0.0f, 0.0f, 0.0f);

    // rows 1..49: compose n = 2*row steps
    for (int t = 0; t < NSAVE; t++) {
        int n = 2 * (t + 1);
        double r0 = 1.0, r1 = 0.0;     // row vector e_u M^i
        double V[4] = {0,0,0,0};
        double S = 0.0;
        for (int i = 0; i < n; i++) {
            int j = n - 1 - i;
            for (int k = 0; k < 4; k++)
                V[k] += r0 * Dlin[j][0][k] + r1 * Dlin[j][1][k];
            S += r0 * E[0] + r1 * E[1];
            double nr0 = r0 * M[0][0] + r1 * M[1][0];
            double nr1 = r0 * M[0][1] + r1 * M[1][1];
            r0 = nr0; r1 = nr1;
        }
        // u_t = (alpha+gamma)*u0 + beta*ud0 + gamma*gm + V.(gm*W)
        kt->a[t + 1] = make_float4((float)(r0 + S), (float)r1, (float)S, 0.0f);
        kt->v[t + 1] = make_float4((float)V[0], (float)V[1], (float)V[2], (float)V[3]);
    }
}

// ---------------- device: packed f32x2 helpers ------------------------------
typedef unsigned long long u64t;

__device__ __forceinline__ u64t pk2(float lo, float hi)
{
    u64t d;
    asm("mov.b64 %0, {%1, %2};" : "=l"(d) : "f"(lo), "f"(hi));
    return d;
}
__device__ __forceinline__ u64t fma2(u64t a, u64t b, u64t c)
{
    u64t d;
    asm("fma.rn.f32x2 %0, %1, %2, %3;" : "=l"(d) : "l"(a), "l"(b), "l"(c));
    return d;
}
__device__ __forceinline__ u64t mul2(u64t a, u64t b)
{
    u64t d;
    asm("mul.rn.f32x2 %0, %1, %2;" : "=l"(d) : "l"(a), "l"(b));
    return d;
}
// Blackwell 256-bit streaming store (st.global.cs.v4.b64, 32B aligned)
__device__ __forceinline__ void st256cs(void* p, u64t a, u64t b, u64t c, u64t d)
{
    asm volatile("st.global.cs.v4.b64 [%0], {%1, %2, %3, %4};"
                 :: "l"(p), "l"(a), "l"(b), "l"(c), "l"(d) : "memory");
}

// ---------------- device: warp-per-batch dense-store kernel -----------------
// Warp = one batch b. Lane l: h = l&1 (action octet), r = l>>1 (row slot 0..15).
// Iteration i (0..2) evaluates row i*16+r and stores 32B -> warp store = 1KB
// contiguous (8 full 128B lines) via one STG.256. Rows 48,49: lanes 0..3 store
// one full 128B line. Row 0 is an identity table row (branch-free).
__global__ void __launch_bounds__(256) ndp_main(
    const KTab kt,
    const float* __restrict__ iu,   // [B, 32] u|ud
    const float* __restrict__ rw,   // [B, 16, 4]
    const float* __restrict__ go,   // [B, 16]
    float* __restrict__ out,        // [B, 50, 16]
    int B)
{
    __shared__ float4 sA[NROW];
    __shared__ float4 sV[NROW];
    {
        int t = threadIdx.x;
        if (t < NROW)                        sA[t] = kt.a[t];
        else if (t >= 64 && t < 64 + NROW)   sV[t - 64] = kt.v[t - 64];
    }
    __syncthreads();

    int b = blockIdx.x * 8 + (threadIdx.x >> 5);   // warp index = batch
    if (b >= B) return;
    int l = threadIdx.x & 31;
    int h = l & 1;          // action octet: components h*8 .. h*8+7
    int r = l >> 1;         // row slot 0..15

    // load this thread's 8 components of u0 / ud0 / g  (2 distinct 32B per warp-LDG)
    const float4 ua = *(const float4*)(iu + b * 32 + h * 8);
    const float4 ub = *(const float4*)(iu + b * 32 + h * 8 + 4);
    const float4 da = *(const float4*)(iu + b * 32 + 16 + h * 8);
    const float4 db = *(const float4*)(iu + b * 32 + 16 + h * 8 + 4);
    const float4 ga = *(const float4*)(go + b * 16 + h * 8);
    const float4 gb = *(const float4*)(go + b * 16 + h * 8 + 4);
    // W rows for actions h*8+j, j=0..7 (4 floats each)
    const float* wp = rw + b * 64 + h * 32;
    const float4 W0 = *(const float4*)(wp);
    const float4 W1 = *(const float4*)(wp + 4);
    const float4 W2 = *(const float4*)(wp + 8);
    const float4 W3 = *(const float4*)(wp + 12);
    const float4 W4 = *(const float4*)(wp + 16);
    const float4 W5 = *(const float4*)(wp + 20);
    const float4 W6 = *(const float4*)(wp + 24);
    const float4 W7 = *(const float4*)(wp + 28);

    const float g0 = ga.x - ua.x, g1 = ga.y - ua.y, g2 = ga.z - ua.z, g3 = ga.w - ua.w;
    const float g4 = gb.x - ub.x, g5 = gb.y - ub.y, g6 = gb.z - ub.z, g7 = gb.w - ub.w;

    // packed per-pair state: pairs (0,1) (2,3) (4,5) (6,7)
    const u64t u0p[4] = { pk2(ua.x, ua.y), pk2(ua.z, ua.w), pk2(ub.x, ub.y), pk2(ub.z, ub.w) };
    const u64t udp[4] = { pk2(da.x, da.y), pk2(da.z, da.w), pk2(db.x, db.y), pk2(db.z, db.w) };
    const u64t gmp[4] = { pk2(g0, g1),     pk2(g2, g3),     pk2(g4, g5),     pk2(g6, g7) };
    // X[p][k] = gm * W[k], packed over the pair
    const u64t X0[4] = { pk2(g0*W0.x, g1*W1.x), pk2(g2*W2.x, g3*W3.x),
                         pk2(g4*W4.x, g5*W5.x), pk2(g6*W6.x, g7*W7.x) };
    const u64t X1[4] = { pk2(g0*W0.y, g1*W1.y), pk2(g2*W2.y, g3*W3.y),
                         pk2(g4*W4.y, g5*W5.y), pk2(g6*W6.y, g7*W7.y) };
    const u64t X2[4] = { pk2(g0*W0.z, g1*W1.z), pk2(g2*W2.z, g3*W3.z),
                         pk2(g4*W4.z, g5*W5.z), pk2(g6*W6.z, g7*W7.z) };
    const u64t X3[4] = { pk2(g0*W0.w, g1*W1.w), pk2(g2*W2.w, g3*W3.w),
                         pk2(g4*W4.w, g5*W5.w), pk2(g6*W6.w, g7*W7.w) };

    float* ob = out + (size_t)b * 800 + h * 8;   // this thread's 32B column

#define ROW_EVAL_ST(row)                                                     \
    {                                                                        \
        const float4 A = sA[row];   /* {Ax, Ay, Az, -} */                    \
        const float4 V = sV[row];                                            \
        const u64t ax = pk2(A.x, A.x), ay = pk2(A.y, A.y), az = pk2(A.z, A.z); \
        const u64t v0 = pk2(V.x, V.x), v1 = pk2(V.y, V.y);                   \
        const u64t v2 = pk2(V.z, V.z), v3 = pk2(V.w, V.w);                   \
        u64t acc[4];                                                         \
        _Pragma("unroll")                                                    \
        for (int p = 0; p < 4; p++) {                                        \
            u64t t0 = mul2(v0, X0[p]);                                       \
            t0 = fma2(v1, X1[p], t0);                                        \
            t0 = fma2(v2, X2[p], t0);                                        \
            t0 = fma2(v3, X3[p], t0);                                        \
            t0 = fma2(az, gmp[p], t0);                                       \
            t0 = fma2(ay, udp[p], t0);                                       \
            t0 = fma2(ax, u0p[p], t0);                                       \
            acc[p] = t0;                                                     \
        }                                                                    \
        st256cs(ob + (row) * 16, acc[0], acc[1], acc[2], acc[3]);            \
    }

    #pragma unroll
    for (int i = 0; i < 3; i++) {
        int row = i * 16 + r;       // rows 0..47, warp store = 1KB contiguous
        ROW_EVAL_ST(row);
    }
    if (l < 4) {                    // rows 48,49: one full 128B line
        int row = 48 + r;           // r = l>>1 in {0,1}
        ROW_EVAL_ST(row);
    }
#undef ROW_EVAL_ST
}

extern "C" void kernel_launch(void* const* d_in, const int* in_sizes, int n_in,
                              void* d_out, int out_size)
{
    const float* iu = (const float*)d_in[0];   // init_u_udot [B, 32]
    const float* rw = (const float*)d_in[1];   // rbf_weights [B, 64]
    const float* go = (const float*)d_in[2];   // goals [B, 16]
    float* out = (float*)d_out;

    int B  = in_sizes[0] / 32;                  // one warp per batch
    int nb = (B + 7) / 8;                       // 8 warps per 256-thread block

    KTab kt;                 // computed on host at capture time only
    build_ktab(&kt);

    ndp_main<<<nb, 256>>>(kt, iu, rw, go, out, B);
}